// round 2
// baseline (speedup 1.0000x reference)
#include <cuda_runtime.h>

// ============================================================================
// Attention_32916629357041 — fp32 baseline (FFMA2 packed pipes)
// Stage 0: transpose w_qkv -> g_wqkvT[d][j], w_out -> g_woutT[k][c]
// Stage 1: per-window fused QKV GEMM + softmax(+rel-pos bias) + attn@V -> g_ao
// Stage 2: out projection g_ao @ w_out^T + b_out -> d_out
// ============================================================================

typedef unsigned long long ull;

#define NB    1024
#define NTOK  64
#define DIM   512
#define NH    8
#define DH    64
#define QKDIM 1536
#define SCALE 0.125f

__device__ float g_wqkvT[DIM * QKDIM];   // [d][j]
__device__ float g_woutT[DIM * DIM];     // [k][c]
__device__ float g_ao[NB * NTOK * DIM];  // attention output, pre-projection

// ---- packed f32x2 helpers ----
__device__ __forceinline__ ull pk2(float x, float y) {
    ull r; asm("mov.b64 %0, {%1, %2};" : "=l"(r) : "f"(x), "f"(y)); return r;
}
__device__ __forceinline__ void fma2(ull& d, ull a, ull b) {
    asm("fma.rn.f32x2 %0, %1, %2, %0;" : "+l"(d) : "l"(a), "l"(b));
}
__device__ __forceinline__ float2 up2(ull v) {
    float2 f; asm("mov.b64 {%0, %1}, %2;" : "=f"(f.x), "=f"(f.y) : "l"(v)); return f;
}

// ============================================================================
__global__ void prep_kernel(const float* __restrict__ wqkv,
                            const float* __restrict__ wout) {
    int stride = gridDim.x * blockDim.x;
    int tid = blockIdx.x * blockDim.x + threadIdx.x;
    for (int idx = tid; idx < QKDIM * DIM; idx += stride) {
        int j = idx >> 9, d = idx & 511;
        g_wqkvT[d * QKDIM + j] = wqkv[idx];
    }
    for (int idx = tid; idx < DIM * DIM; idx += stride) {
        int c = idx >> 9, k = idx & 511;
        g_woutT[k * DIM + c] = wout[idx];
    }
}

// ============================================================================
// Stage 1: one CTA per window (grid 1024, 256 threads, ~223 KB smem)
// ============================================================================
#define XST 516
#define WST 200
#define QST 204
#define AST 68
#define SM1_FLOATS (64*XST + 32*WST + 64*QST + 64*AST + 240)
#define SM1_BYTES  (SM1_FLOATS * 4)

__global__ void __launch_bounds__(256, 1)
attn_kernel(const float* __restrict__ x, const float* __restrict__ Mat) {
    extern __shared__ float sm[];
    float* xs   = sm;                  // [64][XST] x window
    float* wt   = xs + 64 * XST;       // [32][WST] weight chunk (192 cols: q|k|v)
    float* qkv  = wt + 32 * WST;       // [64][QST] cols 0-63 q, 64-127 k, 128-191 v
    float* attn = qkv + 64 * QST;      // [64][AST]
    float* mats = attn + 64 * AST;     // 225 bias values

    const int b = blockIdx.x, t = threadIdx.x;

    const float* xb = x + b * (NTOK * DIM);
    for (int idx = t; idx < NTOK * DIM; idx += 256)
        xs[(idx >> 9) * XST + (idx & 511)] = xb[idx];
    if (t < 225) mats[t] = Mat[t];
    __syncthreads();

    const int tx = t & 15, ty = t >> 4;
    const int gi0 = ty * 4, gj0 = tx * 12;   // QKV GEMM micro-tile 4i x 12j
    const int ai0 = ty * 4, tj  = tx;        // attention rows / col-lane
    const int d0  = tx * 4;                  // attn@v output cols

    for (int h = 0; h < NH; ++h) {
        // ---------- QKV GEMM: [64,512] x [512,192] ----------
        ull acc[4][6];
        #pragma unroll
        for (int r = 0; r < 4; ++r)
            #pragma unroll
            for (int c = 0; c < 6; ++c) acc[r][c] = 0ULL;

        for (int k0 = 0; k0 < DIM; k0 += 32) {
            #pragma unroll
            for (int l = 0; l < 24; ++l) {
                int idx = t + l * 256;                  // 0..6143
                int dd = idx / 192, jj = idx - dd * 192;
                int seg = jj >> 6, u = jj & 63;         // 0:q 1:k 2:v
                wt[dd * WST + jj] =
                    g_wqkvT[(k0 + dd) * QKDIM + seg * 512 + h * 64 + u];
            }
            __syncthreads();
            #pragma unroll 8
            for (int dd = 0; dd < 32; ++dd) {
                float a0 = xs[(gi0 + 0) * XST + k0 + dd];
                float a1 = xs[(gi0 + 1) * XST + k0 + dd];
                float a2 = xs[(gi0 + 2) * XST + k0 + dd];
                float a3 = xs[(gi0 + 3) * XST + k0 + dd];
                ull pa0 = pk2(a0, a0), pa1 = pk2(a1, a1);
                ull pa2 = pk2(a2, a2), pa3 = pk2(a3, a3);
                const float* wr = wt + dd * WST + gj0;
                float4 w0 = *(const float4*)(wr);
                float4 w1 = *(const float4*)(wr + 4);
                float4 w2 = *(const float4*)(wr + 8);
                ull wp0 = pk2(w0.x, w0.y), wp1 = pk2(w0.z, w0.w);
                ull wp2 = pk2(w1.x, w1.y), wp3 = pk2(w1.z, w1.w);
                ull wp4 = pk2(w2.x, w2.y), wp5 = pk2(w2.z, w2.w);
                fma2(acc[0][0], pa0, wp0); fma2(acc[0][1], pa0, wp1);
                fma2(acc[0][2], pa0, wp2); fma2(acc[0][3], pa0, wp3);
                fma2(acc[0][4], pa0, wp4); fma2(acc[0][5], pa0, wp5);
                fma2(acc[1][0], pa1, wp0); fma2(acc[1][1], pa1, wp1);
                fma2(acc[1][2], pa1, wp2); fma2(acc[1][3], pa1, wp3);
                fma2(acc[1][4], pa1, wp4); fma2(acc[1][5], pa1, wp5);
                fma2(acc[2][0], pa2, wp0); fma2(acc[2][1], pa2, wp1);
                fma2(acc[2][2], pa2, wp2); fma2(acc[2][3], pa2, wp3);
                fma2(acc[2][4], pa2, wp4); fma2(acc[2][5], pa2, wp5);
                fma2(acc[3][0], pa3, wp0); fma2(acc[3][1], pa3, wp1);
                fma2(acc[3][2], pa3, wp2); fma2(acc[3][3], pa3, wp3);
                fma2(acc[3][4], pa3, wp4); fma2(acc[3][5], pa3, wp5);
            }
            __syncthreads();
        }
        #pragma unroll
        for (int r = 0; r < 4; ++r) {
            #pragma unroll
            for (int c = 0; c < 6; ++c) {
                float2 v = up2(acc[r][c]);
                int jj = gj0 + c * 2;
                float s0 = (jj     < 64) ? SCALE : 1.f;
                float s1 = (jj + 1 < 64) ? SCALE : 1.f;
                qkv[(gi0 + r) * QST + jj]     = v.x * s0;
                qkv[(gi0 + r) * QST + jj + 1] = v.y * s1;
            }
        }
        __syncthreads();

        // ---------- sim = q k^T + bias; softmax ----------
        {
            ull s2[4][4];
            #pragma unroll
            for (int r = 0; r < 4; ++r)
                #pragma unroll
                for (int c = 0; c < 4; ++c) s2[r][c] = 0ULL;

            #pragma unroll 4
            for (int dq = 0; dq < 16; ++dq) {
                float4 qv[4], kv[4];
                #pragma unroll
                for (int r = 0; r < 4; ++r)
                    qv[r] = *(const float4*)(qkv + (ai0 + r) * QST + 4 * dq);
                #pragma unroll
                for (int c = 0; c < 4; ++c)
                    kv[c] = *(const float4*)(qkv + (tj + 16 * c) * QST + 64 + 4 * dq);
                #pragma unroll
                for (int r = 0; r < 4; ++r) {
                    ull q01 = pk2(qv[r].x, qv[r].y), q23 = pk2(qv[r].z, qv[r].w);
                    #pragma unroll
                    for (int c = 0; c < 4; ++c) {
                        fma2(s2[r][c], q01, pk2(kv[c].x, kv[c].y));
                        fma2(s2[r][c], q23, pk2(kv[c].z, kv[c].w));
                    }
                }
            }
            #pragma unroll
            for (int r = 0; r < 4; ++r) {
                int i = ai0 + r;
                int r1 = i >> 3, c1 = i & 7;
                float sim[4];
                #pragma unroll
                for (int c = 0; c < 4; ++c) {
                    int j = tj + 16 * c;
                    int r2 = j >> 3, c2 = j & 7;
                    float2 p = up2(s2[r][c]);
                    // bias[i][j] = Mat[(coords[j]-coords[i]+7) flattened]
                    sim[c] = p.x + p.y + mats[(r2 - r1 + 7) * 15 + (c2 - c1 + 7)];
                }
                float m = fmaxf(fmaxf(sim[0], sim[1]), fmaxf(sim[2], sim[3]));
                m = fmaxf(m, __shfl_xor_sync(0xffffffffu, m, 1));
                m = fmaxf(m, __shfl_xor_sync(0xffffffffu, m, 2));
                m = fmaxf(m, __shfl_xor_sync(0xffffffffu, m, 4));
                m = fmaxf(m, __shfl_xor_sync(0xffffffffu, m, 8));
                float e0 = __expf(sim[0] - m), e1 = __expf(sim[1] - m);
                float e2 = __expf(sim[2] - m), e3 = __expf(sim[3] - m);
                float s = e0 + e1 + e2 + e3;
                s += __shfl_xor_sync(0xffffffffu, s, 1);
                s += __shfl_xor_sync(0xffffffffu, s, 2);
                s += __shfl_xor_sync(0xffffffffu, s, 4);
                s += __shfl_xor_sync(0xffffffffu, s, 8);
                float inv = 1.f / s;
                attn[(ai0 + r) * AST + tj]      = e0 * inv;
                attn[(ai0 + r) * AST + tj + 16] = e1 * inv;
                attn[(ai0 + r) * AST + tj + 32] = e2 * inv;
                attn[(ai0 + r) * AST + tj + 48] = e3 * inv;
            }
        }
        __syncthreads();

        // ---------- out = attn @ v ----------
        {
            ull o2[4][2];
            #pragma unroll
            for (int r = 0; r < 4; ++r) { o2[r][0] = 0ULL; o2[r][1] = 0ULL; }
            #pragma unroll 4
            for (int j = 0; j < 64; ++j) {
                float4 vv = *(const float4*)(qkv + j * QST + 128 + d0);
                ull vp0 = pk2(vv.x, vv.y), vp1 = pk2(vv.z, vv.w);
                #pragma unroll
                for (int r = 0; r < 4; ++r) {
                    float a = attn[(ai0 + r) * AST + j];
                    ull pa = pk2(a, a);
                    fma2(o2[r][0], pa, vp0);
                    fma2(o2[r][1], pa, vp1);
                }
            }
            float* ob = g_ao + (size_t)b * NTOK * DIM;
            #pragma unroll
            for (int r = 0; r < 4; ++r) {
                float2 lo = up2(o2[r][0]), hi = up2(o2[r][1]);
                float4 o = make_float4(lo.x, lo.y, hi.x, hi.y);
                *(float4*)(ob + (ai0 + r) * DIM + h * 64 + d0) = o;
            }
        }
        __syncthreads();
    }
}

// ============================================================================
// Stage 2: y = g_ao @ w_out^T + b_out. CTA tile 64r x 128c, micro 8r x 4c.
// ============================================================================
__global__ void __launch_bounds__(256)
proj_kernel(const float* __restrict__ bias, float* __restrict__ y) {
    __shared__ float ast[64 * 33];
    __shared__ float wst[32 * 132];
    const int t = threadIdx.x;
    const int rt = blockIdx.x * 64;
    const int ct = blockIdx.y * 128;
    const int tx = t & 31, ty = t >> 5;
    const int r0 = ty * 8, c0 = tx * 4;

    ull acc[8][2];
    #pragma unroll
    for (int r = 0; r < 8; ++r) { acc[r][0] = 0ULL; acc[r][1] = 0ULL; }

    for (int k0 = 0; k0 < DIM; k0 += 32) {
        #pragma unroll
        for (int l = 0; l < 8; ++l) {
            int idx = t + l * 256;                 // 0..2047
            int r = idx >> 5, kk = idx & 31;
            ast[r * 33 + kk] = g_ao[(size_t)(rt + r) * DIM + k0 + kk];
        }
        #pragma unroll
        for (int l = 0; l < 16; ++l) {
            int idx = t + l * 256;                 // 0..4095
            int kk = idx >> 7, c = idx & 127;
            wst[kk * 132 + c] = g_woutT[(k0 + kk) * DIM + ct + c];
        }
        __syncthreads();
        #pragma unroll 8
        for (int kk = 0; kk < 32; ++kk) {
            float4 w = *(const float4*)(wst + kk * 132 + c0);
            ull w0 = pk2(w.x, w.y), w1 = pk2(w.z, w.w);
            #pragma unroll
            for (int r = 0; r < 8; ++r) {
                float a = ast[(r0 + r) * 33 + kk];
                ull pa = pk2(a, a);
                fma2(acc[r][0], pa, w0);
                fma2(acc[r][1], pa, w1);
            }
        }
        __syncthreads();
    }
    float4 bz = *(const float4*)(bias + ct + c0);
    #pragma unroll
    for (int r = 0; r < 8; ++r) {
        float2 lo = up2(acc[r][0]), hi = up2(acc[r][1]);
        float4 o = make_float4(lo.x + bz.x, lo.y + bz.y, hi.x + bz.z, hi.y + bz.w);
        *(float4*)(y + (size_t)(rt + r0 + r) * DIM + ct + c0) = o;
    }
}

// ============================================================================
extern "C" void kernel_launch(void* const* d_in, const int* in_sizes, int n_in,
                              void* d_out, int out_size) {
    const float* x    = (const float*)d_in[0];
    const float* wqkv = (const float*)d_in[1];
    const float* wout = (const float*)d_in[2];
    const float* bout = (const float*)d_in[3];
    const float* Mat  = (const float*)d_in[4];
    float* y = (float*)d_out;

    static bool attr_set = false;
    if (!attr_set) {
        cudaFuncSetAttribute(attn_kernel,
                             cudaFuncAttributeMaxDynamicSharedMemorySize, SM1_BYTES);
        attr_set = true;
    }

    prep_kernel<<<256, 256>>>(wqkv, wout);
    attn_kernel<<<NB, 256, SM1_BYTES>>>(x, Mat);
    proj_kernel<<<dim3(NB * NTOK / 64, DIM / 128), 256>>>(bout, y);
}

// round 5
// speedup vs baseline: 1.9732x; 1.9732x over previous
#include <cuda_runtime.h>
#include <cuda_bf16.h>
#include <cstdint>

// ============================================================================
// Attention_32916629357041 — mma.sync bf16 split-precision GEMMs (sm_100 base)
//   prep:  fp32 -> bf16 hi/lo splits (x, w_qkv [q rows pre-scaled], w_out)
//   gemm1: qkv = x @ w_qkv^T   (mma.sync m16n8k16, 3-term split, fp32 acc)
//   attn:  per-window softmax core (fp32, writes ao as bf16 hi/lo)
//   gemm2: y = ao @ w_out^T + b_out
// ============================================================================

typedef unsigned long long ull;

#define NB    1024
#define NTOK  64
#define DIM   512
#define QKDIM 1536
#define NROWS (NB * NTOK)          // 65536
#define SCALE 0.125f

// ---------------- device scratch ----------------
__device__ __nv_bfloat16 g_x_hi[(size_t)NROWS * DIM];
__device__ __nv_bfloat16 g_x_lo[(size_t)NROWS * DIM];
__device__ __nv_bfloat16 g_w1_hi[QKDIM * DIM];
__device__ __nv_bfloat16 g_w1_lo[QKDIM * DIM];
__device__ __nv_bfloat16 g_w2_hi[DIM * DIM];
__device__ __nv_bfloat16 g_w2_lo[DIM * DIM];
__device__ float         g_qkv[(size_t)NROWS * QKDIM];
__device__ __nv_bfloat16 g_ao_hi[(size_t)NROWS * DIM];
__device__ __nv_bfloat16 g_ao_lo[(size_t)NROWS * DIM];

// ---------------- helpers ----------------
__device__ __forceinline__ ull pk2(float x, float y) {
    ull r; asm("mov.b64 %0, {%1, %2};" : "=l"(r) : "f"(x), "f"(y)); return r;
}
__device__ __forceinline__ void fma2(ull& d, ull a, ull b) {
    asm("fma.rn.f32x2 %0, %1, %2, %0;" : "+l"(d) : "l"(a), "l"(b));
}
__device__ __forceinline__ float2 up2(ull v) {
    float2 f; asm("mov.b64 {%0, %1}, %2;" : "=f"(f.x), "=f"(f.y) : "l"(v)); return f;
}
__device__ __forceinline__ uint32_t smem_u32(const void* p) {
    uint32_t a;
    asm("{ .reg .u64 t; cvta.to.shared.u64 t, %1; cvt.u32.u64 %0, t; }" : "=r"(a) : "l"(p));
    return a;
}
__device__ __forceinline__ void cpa16(uint32_t dst, const void* src) {
    asm volatile("cp.async.cg.shared.global [%0], [%1], 16;" :: "r"(dst), "l"(src));
}
__device__ __forceinline__ void cpa_commit() {
    asm volatile("cp.async.commit_group;" ::: "memory");
}
template <int N>
__device__ __forceinline__ void cpa_wait() {
    asm volatile("cp.async.wait_group %0;" :: "n"(N) : "memory");
}
__device__ __forceinline__ void ldsm4(uint32_t* r, uint32_t addr) {
    asm volatile("ldmatrix.sync.aligned.m8n8.x4.shared.b16 {%0,%1,%2,%3}, [%4];"
                 : "=r"(r[0]), "=r"(r[1]), "=r"(r[2]), "=r"(r[3]) : "r"(addr));
}
__device__ __forceinline__ void mma16816(float* c, const uint32_t* a, const uint32_t* b) {
    asm volatile(
        "mma.sync.aligned.m16n8k16.row.col.f32.bf16.bf16.f32 "
        "{%0,%1,%2,%3}, {%4,%5,%6,%7}, {%8,%9}, {%0,%1,%2,%3};"
        : "+f"(c[0]), "+f"(c[1]), "+f"(c[2]), "+f"(c[3])
        : "r"(a[0]), "r"(a[1]), "r"(a[2]), "r"(a[3]), "r"(b[0]), "r"(b[1]));
}

// ============================================================================
// prep: fp32 -> bf16 hi/lo
// ============================================================================
__device__ __forceinline__ void split_store(float v, __nv_bfloat16* hi,
                                            __nv_bfloat16* lo, size_t i) {
    __nv_bfloat16 h = __float2bfloat16(v);
    hi[i] = h;
    lo[i] = __float2bfloat16(v - __bfloat162float(h));
}

__global__ void prep_kernel(const float* __restrict__ x,
                            const float* __restrict__ w1,
                            const float* __restrict__ w2) {
    size_t stride = (size_t)gridDim.x * blockDim.x;
    size_t tid = (size_t)blockIdx.x * blockDim.x + threadIdx.x;
    for (size_t i = tid; i < (size_t)NROWS * DIM; i += stride)
        split_store(x[i], g_x_hi, g_x_lo, i);
    for (size_t i = tid; i < (size_t)QKDIM * DIM; i += stride) {
        float v = w1[i] * ((i < (size_t)DIM * DIM) ? SCALE : 1.0f);  // fold q-scale
        split_store(v, g_w1_hi, g_w1_lo, i);
    }
    for (size_t i = tid; i < (size_t)DIM * DIM; i += stride)
        split_store(w2[i], g_w2_hi, g_w2_lo, i);
}

// ============================================================================
// gemm: C[m][n] = sum_k A[m][k]*B[n][k], K=512, bf16 hi/lo 3-term, fp32 acc
// CTA tile 128x128, 8 warps (4M x 2N), each warp 32x64. k-chunk 32,
// 2-stage cp.async pipeline. smem rows padded to 80B (conflict-free ldmatrix).
// ============================================================================
#define KC    32
#define ROWB  80                  // bytes per smem row (32 bf16 + 8 pad)
#define MATB  (128 * ROWB)        // 10240 per matrix
#define STG   (4 * MATB)          // A_hi A_lo B_hi B_lo per stage
#define GSMEM (2 * STG)           // 81920

struct GemmSrc { const __nv_bfloat16 *Ah, *Al, *Bh, *Bl; };

__device__ __forceinline__ void issue_stage(const GemmSrc& S, size_t arow0,
                                            size_t brow0, int kc, uint32_t sb,
                                            int t) {
    const __nv_bfloat16* mats[4] = {S.Ah, S.Al, S.Bh, S.Bl};
    size_t row0s[4] = {arow0, arow0, brow0, brow0};
    #pragma unroll
    for (int m = 0; m < 4; ++m) {
        #pragma unroll
        for (int l = 0; l < 2; ++l) {
            int idx = t + l * 256;            // 0..511
            int r = idx >> 2, c16 = idx & 3;
            const __nv_bfloat16* src =
                mats[m] + (row0s[m] + r) * DIM + kc * KC + c16 * 8;
            cpa16(sb + m * MATB + r * ROWB + c16 * 16, src);
        }
    }
    cpa_commit();
}

__global__ void __launch_bounds__(256, 1)
gemm_kernel(int which, const float* __restrict__ bias, float* __restrict__ cext) {
    extern __shared__ char sm[];
    const uint32_t sbase = smem_u32(sm);

    const int t = threadIdx.x, w = t >> 5, lane = t & 31;
    const int wm = w & 3, wn = w >> 2;
    const int nt = blockIdx.x, rt = blockIdx.y;

    GemmSrc S;
    float* C; int ldc;
    if (which == 0) { S = {g_x_hi,  g_x_lo,  g_w1_hi, g_w1_lo};
                      C = g_qkv; ldc = QKDIM; }
    else            { S = {g_ao_hi, g_ao_lo, g_w2_hi, g_w2_lo};
                      C = cext;  ldc = DIM; }
    const size_t arow0 = (size_t)rt * 128;
    const size_t brow0 = (size_t)nt * 128;

    float acc[2][8][4];
    #pragma unroll
    for (int mi = 0; mi < 2; ++mi)
        #pragma unroll
        for (int ni = 0; ni < 8; ++ni)
            #pragma unroll
            for (int e = 0; e < 4; ++e) acc[mi][ni][e] = 0.f;

    // ldmatrix lane addressing (constant offsets within a stage)
    const int a_row  = wm * 32 + (lane & 15);
    const int a_koff = (lane >> 4) * 16;
    const int b_lr = lane & 7, b_g2 = lane >> 3;
    const int b_nrow_base = wn * 64 + b_lr + (b_g2 >> 1) * 8;
    const int b_koff = (b_g2 & 1) * 16;

    const int NKC = DIM / KC;   // 16
    issue_stage(S, arow0, brow0, 0, sbase, t);

    for (int kc = 0; kc < NKC; ++kc) {
        const uint32_t sb = sbase + (kc & 1) * STG;
        if (kc + 1 < NKC) {
            issue_stage(S, arow0, brow0, kc + 1, sbase + ((kc + 1) & 1) * STG, t);
            cpa_wait<1>();
        } else {
            cpa_wait<0>();
        }
        __syncthreads();

        #pragma unroll
        for (int k16 = 0; k16 < 2; ++k16) {
            const int kb = k16 * 32;      // byte offset of this k16 in the row
            uint32_t ah[2][4], al[2][4];
            #pragma unroll
            for (int mi = 0; mi < 2; ++mi) {
                uint32_t ad = sb + (a_row + mi * 16) * ROWB + kb + a_koff;
                ldsm4(ah[mi], ad);
                ldsm4(al[mi], ad + MATB);
            }
            uint32_t bh[4][4], bl[4][4];
            #pragma unroll
            for (int g = 0; g < 4; ++g) {
                uint32_t bd = sb + 2 * MATB + (b_nrow_base + g * 16) * ROWB + kb + b_koff;
                ldsm4(bh[g], bd);
                ldsm4(bl[g], bd + MATB);
            }
            #pragma unroll
            for (int mi = 0; mi < 2; ++mi) {
                #pragma unroll
                for (int g = 0; g < 4; ++g) {
                    mma16816(acc[mi][2 * g],     ah[mi], bh[g]);
                    mma16816(acc[mi][2 * g + 1], ah[mi], bh[g] + 2);
                    mma16816(acc[mi][2 * g],     ah[mi], bl[g]);
                    mma16816(acc[mi][2 * g + 1], ah[mi], bl[g] + 2);
                    mma16816(acc[mi][2 * g],     al[mi], bh[g]);
                    mma16816(acc[mi][2 * g + 1], al[mi], bh[g] + 2);
                }
            }
        }
        __syncthreads();
    }

    // ---- epilogue: direct register -> gmem stores ----
    const int qr = lane >> 2, qc = lane & 3;
    #pragma unroll
    for (int mi = 0; mi < 2; ++mi) {
        #pragma unroll
        for (int ni = 0; ni < 8; ++ni) {
            size_t row = arow0 + wm * 32 + mi * 16 + qr;
            int col = nt * 128 + wn * 64 + ni * 8 + qc * 2;
            float2 v0 = make_float2(acc[mi][ni][0], acc[mi][ni][1]);
            float2 v1 = make_float2(acc[mi][ni][2], acc[mi][ni][3]);
            if (bias != nullptr) {
                float2 bz = *(const float2*)(bias + col);
                v0.x += bz.x; v0.y += bz.y; v1.x += bz.x; v1.y += bz.y;
            }
            *(float2*)(C + row * ldc + col)       = v0;
            *(float2*)(C + (row + 8) * ldc + col) = v1;
        }
    }
}

// ============================================================================
// attention core: per window, fp32. Reads g_qkv, writes g_ao_{hi,lo}.
// ============================================================================
#define AQ 68
#define ASMEM ((4 * 64 * AQ + 240) * 4)

__global__ void __launch_bounds__(256, 1)
attn_kernel(const float* __restrict__ Mat) {
    extern __shared__ float smf[];
    float* qs   = smf;
    float* ks   = qs + 64 * AQ;
    float* vs   = ks + 64 * AQ;
    float* as_  = vs + 64 * AQ;
    float* mats = as_ + 64 * AQ;

    const int b = blockIdx.x, t = threadIdx.x;
    if (t < 225) mats[t] = Mat[t];

    const int tx = t & 15, ty = t >> 4;
    const int ai0 = ty * 4, tj = tx, d0 = tx * 4;
    const float* qg = g_qkv + (size_t)b * NTOK * QKDIM;

    for (int h = 0; h < 8; ++h) {
        #pragma unroll
        for (int l = 0; l < 4; ++l) {
            int idx = t + l * 256;           // 0..1023
            int row = idx >> 4, c4 = idx & 15;
            const float* rp = qg + (size_t)row * QKDIM + h * 64 + c4 * 4;
            *(float4*)(qs + row * AQ + c4 * 4) = *(const float4*)(rp);
            *(float4*)(ks + row * AQ + c4 * 4) = *(const float4*)(rp + 512);
            *(float4*)(vs + row * AQ + c4 * 4) = *(const float4*)(rp + 1024);
        }
        __syncthreads();

        // ---- sim = q k^T + bias; softmax ----
        {
            ull s2[4][4];
            #pragma unroll
            for (int r = 0; r < 4; ++r)
                #pragma unroll
                for (int c = 0; c < 4; ++c) s2[r][c] = 0ULL;

            #pragma unroll 4
            for (int dq = 0; dq < 16; ++dq) {
                float4 qv[4], kv[4];
                #pragma unroll
                for (int r = 0; r < 4; ++r)
                    qv[r] = *(const float4*)(qs + (ai0 + r) * AQ + 4 * dq);
                #pragma unroll
                for (int c = 0; c < 4; ++c)
                    kv[c] = *(const float4*)(ks + (tj + 16 * c) * AQ + 4 * dq);
                #pragma unroll
                for (int r = 0; r < 4; ++r) {
                    ull q01 = pk2(qv[r].x, qv[r].y), q23 = pk2(qv[r].z, qv[r].w);
                    #pragma unroll
                    for (int c = 0; c < 4; ++c) {
                        fma2(s2[r][c], q01, pk2(kv[c].x, kv[c].y));
                        fma2(s2[r][c], q23, pk2(kv[c].z, kv[c].w));
                    }
                }
            }
            #pragma unroll
            for (int r = 0; r < 4; ++r) {
                int i = ai0 + r;
                int r1 = i >> 3, c1 = i & 7;
                float sim[4];
                #pragma unroll
                for (int c = 0; c < 4; ++c) {
                    int j = tj + 16 * c;
                    int r2 = j >> 3, c2 = j & 7;
                    float2 p = up2(s2[r][c]);
                    sim[c] = p.x + p.y + mats[(r2 - r1 + 7) * 15 + (c2 - c1 + 7)];
                }
                float m = fmaxf(fmaxf(sim[0], sim[1]), fmaxf(sim[2], sim[3]));
                m = fmaxf(m, __shfl_xor_sync(0xffffffffu, m, 1));
                m = fmaxf(m, __shfl_xor_sync(0xffffffffu, m, 2));
                m = fmaxf(m, __shfl_xor_sync(0xffffffffu, m, 4));
                m = fmaxf(m, __shfl_xor_sync(0xffffffffu, m, 8));
                float e0 = __expf(sim[0] - m), e1 = __expf(sim[1] - m);
                float e2 = __expf(sim[2] - m), e3 = __expf(sim[3] - m);
                float s = e0 + e1 + e2 + e3;
                s += __shfl_xor_sync(0xffffffffu, s, 1);
                s += __shfl_xor_sync(0xffffffffu, s, 2);
                s += __shfl_xor_sync(0xffffffffu, s, 4);
                s += __shfl_xor_sync(0xffffffffu, s, 8);
                float inv = 1.f / s;
                as_[(ai0 + r) * AQ + tj]      = e0 * inv;
                as_[(ai0 + r) * AQ + tj + 16] = e1 * inv;
                as_[(ai0 + r) * AQ + tj + 32] = e2 * inv;
                as_[(ai0 + r) * AQ + tj + 48] = e3 * inv;
            }
        }
        __syncthreads();

        // ---- out = attn @ v ; split to bf16 hi/lo ----
        {
            ull o2[4][2];
            #pragma unroll
            for (int r = 0; r < 4; ++r) { o2[r][0] = 0ULL; o2[r][1] = 0ULL; }
            #pragma unroll 4
            for (int j = 0; j < 64; ++j) {
                float4 vv = *(const float4*)(vs + j * AQ + d0);
                ull vp0 = pk2(vv.x, vv.y), vp1 = pk2(vv.z, vv.w);
                #pragma unroll
                for (int r = 0; r < 4; ++r) {
                    float a = as_[(ai0 + r) * AQ + j];
                    ull pa = pk2(a, a);
                    fma2(o2[r][0], pa, vp0);
                    fma2(o2[r][1], pa, vp1);
                }
            }
            #pragma unroll
            for (int r = 0; r < 4; ++r) {
                float2 lo2 = up2(o2[r][0]), hi2 = up2(o2[r][1]);
                float o[4] = {lo2.x, lo2.y, hi2.x, hi2.y};
                size_t off = ((size_t)b * NTOK + ai0 + r) * DIM + h * 64 + d0;
                __nv_bfloat16 bh4[4], bl4[4];
                #pragma unroll
                for (int c = 0; c < 4; ++c) {
                    bh4[c] = __float2bfloat16(o[c]);
                    bl4[c] = __float2bfloat16(o[c] - __bfloat162float(bh4[c]));
                }
                *(__nv_bfloat162*)(g_ao_hi + off)     = __halves2bfloat162(bh4[0], bh4[1]);
                *(__nv_bfloat162*)(g_ao_hi + off + 2) = __halves2bfloat162(bh4[2], bh4[3]);
                *(__nv_bfloat162*)(g_ao_lo + off)     = __halves2bfloat162(bl4[0], bl4[1]);
                *(__nv_bfloat162*)(g_ao_lo + off + 2) = __halves2bfloat162(bl4[2], bl4[3]);
            }
        }
        __syncthreads();
    }
}

// ============================================================================
extern "C" void kernel_launch(void* const* d_in, const int* in_sizes, int n_in,
                              void* d_out, int out_size) {
    const float* x    = (const float*)d_in[0];
    const float* wqkv = (const float*)d_in[1];
    const float* wout = (const float*)d_in[2];
    const float* bout = (const float*)d_in[3];
    const float* Mat  = (const float*)d_in[4];
    float* y = (float*)d_out;

    static bool attr_set = false;
    if (!attr_set) {
        cudaFuncSetAttribute(gemm_kernel,
                             cudaFuncAttributeMaxDynamicSharedMemorySize, GSMEM);
        cudaFuncSetAttribute(attn_kernel,
                             cudaFuncAttributeMaxDynamicSharedMemorySize, ASMEM);
        attr_set = true;
    }

    prep_kernel<<<8192, 256>>>(x, wqkv, wout);
    gemm_kernel<<<dim3(QKDIM / 128, NROWS / 128), 256, GSMEM>>>(0, nullptr, y);
    attn_kernel<<<NB, 256, ASMEM>>>(Mat);
    gemm_kernel<<<dim3(DIM / 128, NROWS / 128), 256, GSMEM>>>(1, bout, y);
}

// round 6
// speedup vs baseline: 2.3447x; 1.1883x over previous
#include <cuda_runtime.h>
#include <cuda_bf16.h>
#include <cstdint>

// ============================================================================
// Attention_32916629357041 — mma.sync bf16 split-precision GEMMs (sm_100 base)
//   prep:  fp32 -> bf16 hi/lo splits (x, w_qkv [q rows pre-scaled], w_out)
//   gemm1: qkv = x @ w_qkv^T   (mma.sync m16n8k16, 3-term split, fp32 acc)
//   attn:  per-window softmax core (fp32, writes ao as bf16 hi/lo)
//   gemm2: y = ao @ w_out^T + b_out
// R6: gemm_kernel capped at 128 regs (__launch_bounds__(256,2)) + JIT B frags
//     so 2 CTAs/SM co-reside (16 warps/SM) to hide mma/ldmatrix latency.
// ============================================================================

typedef unsigned long long ull;

#define NB    1024
#define NTOK  64
#define DIM   512
#define QKDIM 1536
#define NROWS (NB * NTOK)          // 65536
#define SCALE 0.125f

// ---------------- device scratch ----------------
__device__ __nv_bfloat16 g_x_hi[(size_t)NROWS * DIM];
__device__ __nv_bfloat16 g_x_lo[(size_t)NROWS * DIM];
__device__ __nv_bfloat16 g_w1_hi[QKDIM * DIM];
__device__ __nv_bfloat16 g_w1_lo[QKDIM * DIM];
__device__ __nv_bfloat16 g_w2_hi[DIM * DIM];
__device__ __nv_bfloat16 g_w2_lo[DIM * DIM];
__device__ float         g_qkv[(size_t)NROWS * QKDIM];
__device__ __nv_bfloat16 g_ao_hi[(size_t)NROWS * DIM];
__device__ __nv_bfloat16 g_ao_lo[(size_t)NROWS * DIM];

// ---------------- helpers ----------------
__device__ __forceinline__ ull pk2(float x, float y) {
    ull r; asm("mov.b64 %0, {%1, %2};" : "=l"(r) : "f"(x), "f"(y)); return r;
}
__device__ __forceinline__ void fma2(ull& d, ull a, ull b) {
    asm("fma.rn.f32x2 %0, %1, %2, %0;" : "+l"(d) : "l"(a), "l"(b));
}
__device__ __forceinline__ float2 up2(ull v) {
    float2 f; asm("mov.b64 {%0, %1}, %2;" : "=f"(f.x), "=f"(f.y) : "l"(v)); return f;
}
__device__ __forceinline__ uint32_t smem_u32(const void* p) {
    uint32_t a;
    asm("{ .reg .u64 t; cvta.to.shared.u64 t, %1; cvt.u32.u64 %0, t; }" : "=r"(a) : "l"(p));
    return a;
}
__device__ __forceinline__ void cpa16(uint32_t dst, const void* src) {
    asm volatile("cp.async.cg.shared.global [%0], [%1], 16;" :: "r"(dst), "l"(src));
}
__device__ __forceinline__ void cpa_commit() {
    asm volatile("cp.async.commit_group;" ::: "memory");
}
template <int N>
__device__ __forceinline__ void cpa_wait() {
    asm volatile("cp.async.wait_group %0;" :: "n"(N) : "memory");
}
__device__ __forceinline__ void ldsm4(uint32_t* r, uint32_t addr) {
    asm volatile("ldmatrix.sync.aligned.m8n8.x4.shared.b16 {%0,%1,%2,%3}, [%4];"
                 : "=r"(r[0]), "=r"(r[1]), "=r"(r[2]), "=r"(r[3]) : "r"(addr));
}
__device__ __forceinline__ void mma16816(float* c, const uint32_t* a, const uint32_t* b) {
    asm volatile(
        "mma.sync.aligned.m16n8k16.row.col.f32.bf16.bf16.f32 "
        "{%0,%1,%2,%3}, {%4,%5,%6,%7}, {%8,%9}, {%0,%1,%2,%3};"
        : "+f"(c[0]), "+f"(c[1]), "+f"(c[2]), "+f"(c[3])
        : "r"(a[0]), "r"(a[1]), "r"(a[2]), "r"(a[3]), "r"(b[0]), "r"(b[1]));
}

// ============================================================================
// prep: fp32 -> bf16 hi/lo
// ============================================================================
__device__ __forceinline__ void split_store(float v, __nv_bfloat16* hi,
                                            __nv_bfloat16* lo, size_t i) {
    __nv_bfloat16 h = __float2bfloat16(v);
    hi[i] = h;
    lo[i] = __float2bfloat16(v - __bfloat162float(h));
}

__global__ void prep_kernel(const float* __restrict__ x,
                            const float* __restrict__ w1,
                            const float* __restrict__ w2) {
    size_t stride = (size_t)gridDim.x * blockDim.x;
    size_t tid = (size_t)blockIdx.x * blockDim.x + threadIdx.x;
    for (size_t i = tid; i < (size_t)NROWS * DIM; i += stride)
        split_store(x[i], g_x_hi, g_x_lo, i);
    for (size_t i = tid; i < (size_t)QKDIM * DIM; i += stride) {
        float v = w1[i] * ((i < (size_t)DIM * DIM) ? SCALE : 1.0f);  // fold q-scale
        split_store(v, g_w1_hi, g_w1_lo, i);
    }
    for (size_t i = tid; i < (size_t)DIM * DIM; i += stride)
        split_store(w2[i], g_w2_hi, g_w2_lo, i);
}

// ============================================================================
// gemm: C[m][n] = sum_k A[m][k]*B[n][k], K=512, bf16 hi/lo 3-term, fp32 acc
// CTA tile 128x128, 8 warps (4M x 2N), each warp 32x64. k-chunk 32,
// 2-stage cp.async pipeline. smem rows padded to 80B (conflict-free ldmatrix).
// ============================================================================
#define KC    32
#define ROWB  80                  // bytes per smem row (32 bf16 + 8 pad)
#define MATB  (128 * ROWB)        // 10240 per matrix
#define STG   (4 * MATB)          // A_hi A_lo B_hi B_lo per stage
#define GSMEM (2 * STG)           // 81920

struct GemmSrc { const __nv_bfloat16 *Ah, *Al, *Bh, *Bl; };

__device__ __forceinline__ void issue_stage(const GemmSrc& S, size_t arow0,
                                            size_t brow0, int kc, uint32_t sb,
                                            int t) {
    const __nv_bfloat16* mats[4] = {S.Ah, S.Al, S.Bh, S.Bl};
    size_t row0s[4] = {arow0, arow0, brow0, brow0};
    #pragma unroll
    for (int m = 0; m < 4; ++m) {
        #pragma unroll
        for (int l = 0; l < 2; ++l) {
            int idx = t + l * 256;            // 0..511
            int r = idx >> 2, c16 = idx & 3;
            const __nv_bfloat16* src =
                mats[m] + (row0s[m] + r) * DIM + kc * KC + c16 * 8;
            cpa16(sb + m * MATB + r * ROWB + c16 * 16, src);
        }
    }
    cpa_commit();
}

__global__ void __launch_bounds__(256, 2)
gemm_kernel(int which, const float* __restrict__ bias, float* __restrict__ cext) {
    extern __shared__ char sm[];
    const uint32_t sbase = smem_u32(sm);

    const int t = threadIdx.x, w = t >> 5, lane = t & 31;
    const int wm = w & 3, wn = w >> 2;
    const int nt = blockIdx.x, rt = blockIdx.y;

    GemmSrc S;
    float* C; int ldc;
    if (which == 0) { S = {g_x_hi,  g_x_lo,  g_w1_hi, g_w1_lo};
                      C = g_qkv; ldc = QKDIM; }
    else            { S = {g_ao_hi, g_ao_lo, g_w2_hi, g_w2_lo};
                      C = cext;  ldc = DIM; }
    const size_t arow0 = (size_t)rt * 128;
    const size_t brow0 = (size_t)nt * 128;

    float acc[2][8][4];
    #pragma unroll
    for (int mi = 0; mi < 2; ++mi)
        #pragma unroll
        for (int ni = 0; ni < 8; ++ni)
            #pragma unroll
            for (int e = 0; e < 4; ++e) acc[mi][ni][e] = 0.f;

    // ldmatrix lane addressing (constant offsets within a stage)
    const int a_row  = wm * 32 + (lane & 15);
    const int a_koff = (lane >> 4) * 16;
    const int b_lr = lane & 7, b_g2 = lane >> 3;
    const int b_nrow_base = wn * 64 + b_lr + (b_g2 >> 1) * 8;
    const int b_koff = (b_g2 & 1) * 16;

    const int NKC = DIM / KC;   // 16
    issue_stage(S, arow0, brow0, 0, sbase, t);

    for (int kc = 0; kc < NKC; ++kc) {
        const uint32_t sb = sbase + (kc & 1) * STG;
        if (kc + 1 < NKC) {
            issue_stage(S, arow0, brow0, kc + 1, sbase + ((kc + 1) & 1) * STG, t);
            cpa_wait<1>();
        } else {
            cpa_wait<0>();
        }
        __syncthreads();

        #pragma unroll
        for (int k16 = 0; k16 < 2; ++k16) {
            const int kb = k16 * 32;      // byte offset of this k16 in the row
            uint32_t ah[2][4], al[2][4];
            #pragma unroll
            for (int mi = 0; mi < 2; ++mi) {
                uint32_t ad = sb + (a_row + mi * 16) * ROWB + kb + a_koff;
                ldsm4(ah[mi], ad);
                ldsm4(al[mi], ad + MATB);
            }
            // JIT B fragments: load per-g, consume immediately (reg pressure)
            #pragma unroll
            for (int g = 0; g < 4; ++g) {
                uint32_t bh[4], bl[4];
                uint32_t bd = sb + 2 * MATB + (b_nrow_base + g * 16) * ROWB + kb + b_koff;
                ldsm4(bh, bd);
                ldsm4(bl, bd + MATB);
                #pragma unroll
                for (int mi = 0; mi < 2; ++mi) {
                    mma16816(acc[mi][2 * g],     ah[mi], bh);
                    mma16816(acc[mi][2 * g + 1], ah[mi], bh + 2);
                    mma16816(acc[mi][2 * g],     ah[mi], bl);
                    mma16816(acc[mi][2 * g + 1], ah[mi], bl + 2);
                    mma16816(acc[mi][2 * g],     al[mi], bh);
                    mma16816(acc[mi][2 * g + 1], al[mi], bh + 2);
                }
            }
        }
        __syncthreads();
    }

    // ---- epilogue: direct register -> gmem stores ----
    const int qr = lane >> 2, qc = lane & 3;
    #pragma unroll
    for (int mi = 0; mi < 2; ++mi) {
        #pragma unroll
        for (int ni = 0; ni < 8; ++ni) {
            size_t row = arow0 + wm * 32 + mi * 16 + qr;
            int col = nt * 128 + wn * 64 + ni * 8 + qc * 2;
            float2 v0 = make_float2(acc[mi][ni][0], acc[mi][ni][1]);
            float2 v1 = make_float2(acc[mi][ni][2], acc[mi][ni][3]);
            if (bias != nullptr) {
                float2 bz = *(const float2*)(bias + col);
                v0.x += bz.x; v0.y += bz.y; v1.x += bz.x; v1.y += bz.y;
            }
            *(float2*)(C + row * ldc + col)       = v0;
            *(float2*)(C + (row + 8) * ldc + col) = v1;
        }
    }
}

// ============================================================================
// attention core: per window, fp32. Reads g_qkv, writes g_ao_{hi,lo}.
// ============================================================================
#define AQ 68
#define ASMEM ((4 * 64 * AQ + 240) * 4)

__global__ void __launch_bounds__(256, 1)
attn_kernel(const float* __restrict__ Mat) {
    extern __shared__ float smf[];
    float* qs   = smf;
    float* ks   = qs + 64 * AQ;
    float* vs   = ks + 64 * AQ;
    float* as_  = vs + 64 * AQ;
    float* mats = as_ + 64 * AQ;

    const int b = blockIdx.x, t = threadIdx.x;
    if (t < 225) mats[t] = Mat[t];

    const int tx = t & 15, ty = t >> 4;
    const int ai0 = ty * 4, tj = tx, d0 = tx * 4;
    const float* qg = g_qkv + (size_t)b * NTOK * QKDIM;

    for (int h = 0; h < 8; ++h) {
        #pragma unroll
        for (int l = 0; l < 4; ++l) {
            int idx = t + l * 256;           // 0..1023
            int row = idx >> 4, c4 = idx & 15;
            const float* rp = qg + (size_t)row * QKDIM + h * 64 + c4 * 4;
            *(float4*)(qs + row * AQ + c4 * 4) = *(const float4*)(rp);
            *(float4*)(ks + row * AQ + c4 * 4) = *(const float4*)(rp + 512);
            *(float4*)(vs + row * AQ + c4 * 4) = *(const float4*)(rp + 1024);
        }
        __syncthreads();

        // ---- sim = q k^T + bias; softmax ----
        {
            ull s2[4][4];
            #pragma unroll
            for (int r = 0; r < 4; ++r)
                #pragma unroll
                for (int c = 0; c < 4; ++c) s2[r][c] = 0ULL;

            #pragma unroll 4
            for (int dq = 0; dq < 16; ++dq) {
                float4 qv[4], kv[4];
                #pragma unroll
                for (int r = 0; r < 4; ++r)
                    qv[r] = *(const float4*)(qs + (ai0 + r) * AQ + 4 * dq);
                #pragma unroll
                for (int c = 0; c < 4; ++c)
                    kv[c] = *(const float4*)(ks + (tj + 16 * c) * AQ + 4 * dq);
                #pragma unroll
                for (int r = 0; r < 4; ++r) {
                    ull q01 = pk2(qv[r].x, qv[r].y), q23 = pk2(qv[r].z, qv[r].w);
                    #pragma unroll
                    for (int c = 0; c < 4; ++c) {
                        fma2(s2[r][c], q01, pk2(kv[c].x, kv[c].y));
                        fma2(s2[r][c], q23, pk2(kv[c].z, kv[c].w));
                    }
                }
            }
            #pragma unroll
            for (int r = 0; r < 4; ++r) {
                int i = ai0 + r;
                int r1 = i >> 3, c1 = i & 7;
                float sim[4];
                #pragma unroll
                for (int c = 0; c < 4; ++c) {
                    int j = tj + 16 * c;
                    int r2 = j >> 3, c2 = j & 7;
                    float2 p = up2(s2[r][c]);
                    sim[c] = p.x + p.y + mats[(r2 - r1 + 7) * 15 + (c2 - c1 + 7)];
                }
                float m = fmaxf(fmaxf(sim[0], sim[1]), fmaxf(sim[2], sim[3]));
                m = fmaxf(m, __shfl_xor_sync(0xffffffffu, m, 1));
                m = fmaxf(m, __shfl_xor_sync(0xffffffffu, m, 2));
                m = fmaxf(m, __shfl_xor_sync(0xffffffffu, m, 4));
                m = fmaxf(m, __shfl_xor_sync(0xffffffffu, m, 8));
                float e0 = __expf(sim[0] - m), e1 = __expf(sim[1] - m);
                float e2 = __expf(sim[2] - m), e3 = __expf(sim[3] - m);
                float s = e0 + e1 + e2 + e3;
                s += __shfl_xor_sync(0xffffffffu, s, 1);
                s += __shfl_xor_sync(0xffffffffu, s, 2);
                s += __shfl_xor_sync(0xffffffffu, s, 4);
                s += __shfl_xor_sync(0xffffffffu, s, 8);
                float inv = 1.f / s;
                as_[(ai0 + r) * AQ + tj]      = e0 * inv;
                as_[(ai0 + r) * AQ + tj + 16] = e1 * inv;
                as_[(ai0 + r) * AQ + tj + 32] = e2 * inv;
                as_[(ai0 + r) * AQ + tj + 48] = e3 * inv;
            }
        }
        __syncthreads();

        // ---- out = attn @ v ; split to bf16 hi/lo ----
        {
            ull o2[4][2];
            #pragma unroll
            for (int r = 0; r < 4; ++r) { o2[r][0] = 0ULL; o2[r][1] = 0ULL; }
            #pragma unroll 4
            for (int j = 0; j < 64; ++j) {
                float4 vv = *(const float4*)(vs + j * AQ + d0);
                ull vp0 = pk2(vv.x, vv.y), vp1 = pk2(vv.z, vv.w);
                #pragma unroll
                for (int r = 0; r < 4; ++r) {
                    float a = as_[(ai0 + r) * AQ + j];
                    ull pa = pk2(a, a);
                    fma2(o2[r][0], pa, vp0);
                    fma2(o2[r][1], pa, vp1);
                }
            }
            #pragma unroll
            for (int r = 0; r < 4; ++r) {
                float2 lo2 = up2(o2[r][0]), hi2 = up2(o2[r][1]);
                float o[4] = {lo2.x, lo2.y, hi2.x, hi2.y};
                size_t off = ((size_t)b * NTOK + ai0 + r) * DIM + h * 64 + d0;
                __nv_bfloat16 bh4[4], bl4[4];
                #pragma unroll
                for (int c = 0; c < 4; ++c) {
                    bh4[c] = __float2bfloat16(o[c]);
                    bl4[c] = __float2bfloat16(o[c] - __bfloat162float(bh4[c]));
                }
                *(__nv_bfloat162*)(g_ao_hi + off)     = __halves2bfloat162(bh4[0], bh4[1]);
                *(__nv_bfloat162*)(g_ao_hi + off + 2) = __halves2bfloat162(bh4[2], bh4[3]);
                *(__nv_bfloat162*)(g_ao_lo + off)     = __halves2bfloat162(bl4[0], bl4[1]);
                *(__nv_bfloat162*)(g_ao_lo + off + 2) = __halves2bfloat162(bl4[2], bl4[3]);
            }
        }
        __syncthreads();
    }
}

// ============================================================================
extern "C" void kernel_launch(void* const* d_in, const int* in_sizes, int n_in,
                              void* d_out, int out_size) {
    const float* x    = (const float*)d_in[0];
    const float* wqkv = (const float*)d_in[1];
    const float* wout = (const float*)d_in[2];
    const float* bout = (const float*)d_in[3];
    const float* Mat  = (const float*)d_in[4];
    float* y = (float*)d_out;

    static bool attr_set = false;
    if (!attr_set) {
        cudaFuncSetAttribute(gemm_kernel,
                             cudaFuncAttributeMaxDynamicSharedMemorySize, GSMEM);
        cudaFuncSetAttribute(attn_kernel,
                             cudaFuncAttributeMaxDynamicSharedMemorySize, ASMEM);
        attr_set = true;
    }

    prep_kernel<<<8192, 256>>>(x, wqkv, wout);
    gemm_kernel<<<dim3(QKDIM / 128, NROWS / 128), 256, GSMEM>>>(0, nullptr, y);
    attn_kernel<<<NB, 256, ASMEM>>>(Mat);
    gemm_kernel<<<dim3(DIM / 128, NROWS / 128), 256, GSMEM>>>(1, bout, y);
}

// round 7
// speedup vs baseline: 2.5619x; 1.0926x over previous
#include <cuda_runtime.h>
#include <cuda_bf16.h>
#include <cstdint>

// ============================================================================
// Attention_32916629357041 — mma.sync bf16 split-precision GEMMs (sm_100 base)
//   prep:  fp32 -> bf16 hi/lo splits (x, w_qkv [q rows pre-scaled], w_out)
//   gemm1: qkv = x @ w_qkv^T   (mma.sync m16n8k16, 3-term split, fp32 acc)
//   attn:  per-window softmax core (fp32, writes ao as bf16 hi/lo)
//   gemm2: y = ao @ w_out^T + b_out
// R7: single-sync GEMM mainloop (compute-then-issue) + attn 2 CTAs/SM.
// ============================================================================

typedef unsigned long long ull;

#define NB    1024
#define NTOK  64
#define DIM   512
#define QKDIM 1536
#define NROWS (NB * NTOK)          // 65536
#define SCALE 0.125f

// ---------------- device scratch ----------------
__device__ __nv_bfloat16 g_x_hi[(size_t)NROWS * DIM];
__device__ __nv_bfloat16 g_x_lo[(size_t)NROWS * DIM];
__device__ __nv_bfloat16 g_w1_hi[QKDIM * DIM];
__device__ __nv_bfloat16 g_w1_lo[QKDIM * DIM];
__device__ __nv_bfloat16 g_w2_hi[DIM * DIM];
__device__ __nv_bfloat16 g_w2_lo[DIM * DIM];
__device__ float         g_qkv[(size_t)NROWS * QKDIM];
__device__ __nv_bfloat16 g_ao_hi[(size_t)NROWS * DIM];
__device__ __nv_bfloat16 g_ao_lo[(size_t)NROWS * DIM];

// ---------------- helpers ----------------
__device__ __forceinline__ ull pk2(float x, float y) {
    ull r; asm("mov.b64 %0, {%1, %2};" : "=l"(r) : "f"(x), "f"(y)); return r;
}
__device__ __forceinline__ void fma2(ull& d, ull a, ull b) {
    asm("fma.rn.f32x2 %0, %1, %2, %0;" : "+l"(d) : "l"(a), "l"(b));
}
__device__ __forceinline__ float2 up2(ull v) {
    float2 f; asm("mov.b64 {%0, %1}, %2;" : "=f"(f.x), "=f"(f.y) : "l"(v)); return f;
}
__device__ __forceinline__ uint32_t smem_u32(const void* p) {
    uint32_t a;
    asm("{ .reg .u64 t; cvta.to.shared.u64 t, %1; cvt.u32.u64 %0, t; }" : "=r"(a) : "l"(p));
    return a;
}
__device__ __forceinline__ void cpa16(uint32_t dst, const void* src) {
    asm volatile("cp.async.cg.shared.global [%0], [%1], 16;" :: "r"(dst), "l"(src));
}
__device__ __forceinline__ void cpa_commit() {
    asm volatile("cp.async.commit_group;" ::: "memory");
}
template <int N>
__device__ __forceinline__ void cpa_wait() {
    asm volatile("cp.async.wait_group %0;" :: "n"(N) : "memory");
}
__device__ __forceinline__ void ldsm4(uint32_t* r, uint32_t addr) {
    asm volatile("ldmatrix.sync.aligned.m8n8.x4.shared.b16 {%0,%1,%2,%3}, [%4];"
                 : "=r"(r[0]), "=r"(r[1]), "=r"(r[2]), "=r"(r[3]) : "r"(addr));
}
__device__ __forceinline__ void mma16816(float* c, const uint32_t* a, const uint32_t* b) {
    asm volatile(
        "mma.sync.aligned.m16n8k16.row.col.f32.bf16.bf16.f32 "
        "{%0,%1,%2,%3}, {%4,%5,%6,%7}, {%8,%9}, {%0,%1,%2,%3};"
        : "+f"(c[0]), "+f"(c[1]), "+f"(c[2]), "+f"(c[3])
        : "r"(a[0]), "r"(a[1]), "r"(a[2]), "r"(a[3]), "r"(b[0]), "r"(b[1]));
}

// ============================================================================
// prep: fp32 -> bf16 hi/lo
// ============================================================================
__device__ __forceinline__ void split_store(float v, __nv_bfloat16* hi,
                                            __nv_bfloat16* lo, size_t i) {
    __nv_bfloat16 h = __float2bfloat16(v);
    hi[i] = h;
    lo[i] = __float2bfloat16(v - __bfloat162float(h));
}

__global__ void prep_kernel(const float* __restrict__ x,
                            const float* __restrict__ w1,
                            const float* __restrict__ w2) {
    size_t stride = (size_t)gridDim.x * blockDim.x;
    size_t tid = (size_t)blockIdx.x * blockDim.x + threadIdx.x;
    for (size_t i = tid; i < (size_t)NROWS * DIM; i += stride)
        split_store(x[i], g_x_hi, g_x_lo, i);
    for (size_t i = tid; i < (size_t)QKDIM * DIM; i += stride) {
        float v = w1[i] * ((i < (size_t)DIM * DIM) ? SCALE : 1.0f);  // fold q-scale
        split_store(v, g_w1_hi, g_w1_lo, i);
    }
    for (size_t i = tid; i < (size_t)DIM * DIM; i += stride)
        split_store(w2[i], g_w2_hi, g_w2_lo, i);
}

// ============================================================================
// gemm: C[m][n] = sum_k A[m][k]*B[n][k], K=512, bf16 hi/lo 3-term, fp32 acc
// CTA tile 128x128, 8 warps (4M x 2N). k-chunk 32, 2-stage cp.async pipeline,
// ONE __syncthreads per chunk (compute-then-issue ordering).
// ============================================================================
#define KC    32
#define ROWB  80                  // bytes per smem row (32 bf16 + 8 pad)
#define MATB  (128 * ROWB)        // 10240 per matrix
#define STG   (4 * MATB)          // A_hi A_lo B_hi B_lo per stage
#define GSMEM (2 * STG)           // 81920

struct GemmSrc { const __nv_bfloat16 *Ah, *Al, *Bh, *Bl; };

__device__ __forceinline__ void issue_stage(const GemmSrc& S, size_t arow0,
                                            size_t brow0, int kc, uint32_t sb,
                                            int t) {
    const __nv_bfloat16* mats[4] = {S.Ah, S.Al, S.Bh, S.Bl};
    size_t row0s[4] = {arow0, arow0, brow0, brow0};
    #pragma unroll
    for (int m = 0; m < 4; ++m) {
        #pragma unroll
        for (int l = 0; l < 2; ++l) {
            int idx = t + l * 256;            // 0..511
            int r = idx >> 2, c16 = idx & 3;
            const __nv_bfloat16* src =
                mats[m] + (row0s[m] + r) * DIM + kc * KC + c16 * 8;
            cpa16(sb + m * MATB + r * ROWB + c16 * 16, src);
        }
    }
    cpa_commit();
}

__global__ void __launch_bounds__(256, 2)
gemm_kernel(int which, const float* __restrict__ bias, float* __restrict__ cext) {
    extern __shared__ char sm[];
    const uint32_t sbase = smem_u32(sm);

    const int t = threadIdx.x, w = t >> 5, lane = t & 31;
    const int wm = w & 3, wn = w >> 2;
    const int nt = blockIdx.x, rt = blockIdx.y;

    GemmSrc S;
    float* C; int ldc;
    if (which == 0) { S = {g_x_hi,  g_x_lo,  g_w1_hi, g_w1_lo};
                      C = g_qkv; ldc = QKDIM; }
    else            { S = {g_ao_hi, g_ao_lo, g_w2_hi, g_w2_lo};
                      C = cext;  ldc = DIM; }
    const size_t arow0 = (size_t)rt * 128;
    const size_t brow0 = (size_t)nt * 128;

    float acc[2][8][4];
    #pragma unroll
    for (int mi = 0; mi < 2; ++mi)
        #pragma unroll
        for (int ni = 0; ni < 8; ++ni)
            #pragma unroll
            for (int e = 0; e < 4; ++e) acc[mi][ni][e] = 0.f;

    // ldmatrix lane addressing
    const int a_row  = wm * 32 + (lane & 15);
    const int a_koff = (lane >> 4) * 16;
    const int b_lr = lane & 7, b_g2 = lane >> 3;
    const int b_nrow_base = wn * 64 + b_lr + (b_g2 >> 1) * 8;
    const int b_koff = (b_g2 & 1) * 16;

    const int NKC = DIM / KC;   // 16
    issue_stage(S, arow0, brow0, 0, sbase, t);

    for (int kc = 0; kc < NKC; ++kc) {
        const uint32_t sb = sbase + (kc & 1) * STG;
        cpa_wait<0>();              // stage kc data landed (thread-local)
        __syncthreads();            // all threads: data visible; buf^1 free
        if (kc + 1 < NKC)
            issue_stage(S, arow0, brow0, kc + 1, sbase + ((kc + 1) & 1) * STG, t);

        #pragma unroll
        for (int k16 = 0; k16 < 2; ++k16) {
            const int kb = k16 * 32;      // byte offset of this k16 in the row
            uint32_t ah[2][4], al[2][4];
            #pragma unroll
            for (int mi = 0; mi < 2; ++mi) {
                uint32_t ad = sb + (a_row + mi * 16) * ROWB + kb + a_koff;
                ldsm4(ah[mi], ad);
                ldsm4(al[mi], ad + MATB);
            }
            // JIT B fragments: load per-g, consume immediately
            #pragma unroll
            for (int g = 0; g < 4; ++g) {
                uint32_t bh[4], bl[4];
                uint32_t bd = sb + 2 * MATB + (b_nrow_base + g * 16) * ROWB + kb + b_koff;
                ldsm4(bh, bd);
                ldsm4(bl, bd + MATB);
                #pragma unroll
                for (int mi = 0; mi < 2; ++mi) {
                    mma16816(acc[mi][2 * g],     ah[mi], bh);
                    mma16816(acc[mi][2 * g + 1], ah[mi], bh + 2);
                    mma16816(acc[mi][2 * g],     ah[mi], bl);
                    mma16816(acc[mi][2 * g + 1], ah[mi], bl + 2);
                    mma16816(acc[mi][2 * g],     al[mi], bh);
                    mma16816(acc[mi][2 * g + 1], al[mi], bh + 2);
                }
            }
        }
    }

    // ---- epilogue: direct register -> gmem stores (no smem use) ----
    const int qr = lane >> 2, qc = lane & 3;
    #pragma unroll
    for (int mi = 0; mi < 2; ++mi) {
        #pragma unroll
        for (int ni = 0; ni < 8; ++ni) {
            size_t row = arow0 + wm * 32 + mi * 16 + qr;
            int col = nt * 128 + wn * 64 + ni * 8 + qc * 2;
            float2 v0 = make_float2(acc[mi][ni][0], acc[mi][ni][1]);
            float2 v1 = make_float2(acc[mi][ni][2], acc[mi][ni][3]);
            if (bias != nullptr) {
                float2 bz = *(const float2*)(bias + col);
                v0.x += bz.x; v0.y += bz.y; v1.x += bz.x; v1.y += bz.y;
            }
            *(float2*)(C + row * ldc + col)       = v0;
            *(float2*)(C + (row + 8) * ldc + col) = v1;
        }
    }
}

// ============================================================================
// attention core: per window, fp32. Reads g_qkv, writes g_ao_{hi,lo}.
// R7: 2 CTAs/SM (smem 2x70.6KB fits 228KB; regs capped 128).
// ============================================================================
#define AQ 68
#define ASMEM ((4 * 64 * AQ + 240) * 4)

__global__ void __launch_bounds__(256, 2)
attn_kernel(const float* __restrict__ Mat) {
    extern __shared__ float smf[];
    float* qs   = smf;
    float* ks   = qs + 64 * AQ;
    float* vs   = ks + 64 * AQ;
    float* as_  = vs + 64 * AQ;
    float* mats = as_ + 64 * AQ;

    const int b = blockIdx.x, t = threadIdx.x;
    if (t < 225) mats[t] = Mat[t];

    const int tx = t & 15, ty = t >> 4;
    const int ai0 = ty * 4, tj = tx, d0 = tx * 4;
    const float* qg = g_qkv + (size_t)b * NTOK * QKDIM;

    for (int h = 0; h < 8; ++h) {
        #pragma unroll
        for (int l = 0; l < 4; ++l) {
            int idx = t + l * 256;           // 0..1023
            int row = idx >> 4, c4 = idx & 15;
            const float* rp = qg + (size_t)row * QKDIM + h * 64 + c4 * 4;
            *(float4*)(qs + row * AQ + c4 * 4) = *(const float4*)(rp);
            *(float4*)(ks + row * AQ + c4 * 4) = *(const float4*)(rp + 512);
            *(float4*)(vs + row * AQ + c4 * 4) = *(const float4*)(rp + 1024);
        }
        __syncthreads();

        // ---- sim = q k^T + bias; softmax ----
        {
            ull s2[4][4];
            #pragma unroll
            for (int r = 0; r < 4; ++r)
                #pragma unroll
                for (int c = 0; c < 4; ++c) s2[r][c] = 0ULL;

            #pragma unroll 4
            for (int dq = 0; dq < 16; ++dq) {
                float4 qv[4], kv[4];
                #pragma unroll
                for (int r = 0; r < 4; ++r)
                    qv[r] = *(const float4*)(qs + (ai0 + r) * AQ + 4 * dq);
                #pragma unroll
                for (int c = 0; c < 4; ++c)
                    kv[c] = *(const float4*)(ks + (tj + 16 * c) * AQ + 4 * dq);
                #pragma unroll
                for (int r = 0; r < 4; ++r) {
                    ull q01 = pk2(qv[r].x, qv[r].y), q23 = pk2(qv[r].z, qv[r].w);
                    #pragma unroll
                    for (int c = 0; c < 4; ++c) {
                        fma2(s2[r][c], q01, pk2(kv[c].x, kv[c].y));
                        fma2(s2[r][c], q23, pk2(kv[c].z, kv[c].w));
                    }
                }
            }
            #pragma unroll
            for (int r = 0; r < 4; ++r) {
                int i = ai0 + r;
                int r1 = i >> 3, c1 = i & 7;
                float sim[4];
                #pragma unroll
                for (int c = 0; c < 4; ++c) {
                    int j = tj + 16 * c;
                    int r2 = j >> 3, c2 = j & 7;
                    float2 p = up2(s2[r][c]);
                    sim[c] = p.x + p.y + mats[(r2 - r1 + 7) * 15 + (c2 - c1 + 7)];
                }
                float m = fmaxf(fmaxf(sim[0], sim[1]), fmaxf(sim[2], sim[3]));
                m = fmaxf(m, __shfl_xor_sync(0xffffffffu, m, 1));
                m = fmaxf(m, __shfl_xor_sync(0xffffffffu, m, 2));
                m = fmaxf(m, __shfl_xor_sync(0xffffffffu, m, 4));
                m = fmaxf(m, __shfl_xor_sync(0xffffffffu, m, 8));
                float e0 = __expf(sim[0] - m), e1 = __expf(sim[1] - m);
                float e2 = __expf(sim[2] - m), e3 = __expf(sim[3] - m);
                float s = e0 + e1 + e2 + e3;
                s += __shfl_xor_sync(0xffffffffu, s, 1);
                s += __shfl_xor_sync(0xffffffffu, s, 2);
                s += __shfl_xor_sync(0xffffffffu, s, 4);
                s += __shfl_xor_sync(0xffffffffu, s, 8);
                float inv = 1.f / s;
                as_[(ai0 + r) * AQ + tj]      = e0 * inv;
                as_[(ai0 + r) * AQ + tj + 16] = e1 * inv;
                as_[(ai0 + r) * AQ + tj + 32] = e2 * inv;
                as_[(ai0 + r) * AQ + tj + 48] = e3 * inv;
            }
        }
        __syncthreads();

        // ---- out = attn @ v ; split to bf16 hi/lo ----
        {
            ull o2[4][2];
            #pragma unroll
            for (int r = 0; r < 4; ++r) { o2[r][0] = 0ULL; o2[r][1] = 0ULL; }
            #pragma unroll 4
            for (int j = 0; j < 64; ++j) {
                float4 vv = *(const float4*)(vs + j * AQ + d0);
                ull vp0 = pk2(vv.x, vv.y), vp1 = pk2(vv.z, vv.w);
                #pragma unroll
                for (int r = 0; r < 4; ++r) {
                    float a = as_[(ai0 + r) * AQ + j];
                    ull pa = pk2(a, a);
                    fma2(o2[r][0], pa, vp0);
                    fma2(o2[r][1], pa, vp1);
                }
            }
            #pragma unroll
            for (int r = 0; r < 4; ++r) {
                float2 lo2 = up2(o2[r][0]), hi2 = up2(o2[r][1]);
                float o[4] = {lo2.x, lo2.y, hi2.x, hi2.y};
                size_t off = ((size_t)b * NTOK + ai0 + r) * DIM + h * 64 + d0;
                __nv_bfloat16 bh4[4], bl4[4];
                #pragma unroll
                for (int c = 0; c < 4; ++c) {
                    bh4[c] = __float2bfloat16(o[c]);
                    bl4[c] = __float2bfloat16(o[c] - __bfloat162float(bh4[c]));
                }
                *(__nv_bfloat162*)(g_ao_hi + off)     = __halves2bfloat162(bh4[0], bh4[1]);
                *(__nv_bfloat162*)(g_ao_hi + off + 2) = __halves2bfloat162(bh4[2], bh4[3]);
                *(__nv_bfloat162*)(g_ao_lo + off)     = __halves2bfloat162(bl4[0], bl4[1]);
                *(__nv_bfloat162*)(g_ao_lo + off + 2) = __halves2bfloat162(bl4[2], bl4[3]);
            }
        }
        __syncthreads();
    }
}

// ============================================================================
extern "C" void kernel_launch(void* const* d_in, const int* in_sizes, int n_in,
                              void* d_out, int out_size) {
    const float* x    = (const float*)d_in[0];
    const float* wqkv = (const float*)d_in[1];
    const float* wout = (const float*)d_in[2];
    const float* bout = (const float*)d_in[3];
    const float* Mat  = (const float*)d_in[4];
    float* y = (float*)d_out;

    static bool attr_set = false;
    if (!attr_set) {
        cudaFuncSetAttribute(gemm_kernel,
                             cudaFuncAttributeMaxDynamicSharedMemorySize, GSMEM);
        cudaFuncSetAttribute(attn_kernel,
                             cudaFuncAttributeMaxDynamicSharedMemorySize, ASMEM);
        attr_set = true;
    }

    prep_kernel<<<8192, 256>>>(x, wqkv, wout);
    gemm_kernel<<<dim3(QKDIM / 128, NROWS / 128), 256, GSMEM>>>(0, nullptr, y);
    attn_kernel<<<NB, 256, ASMEM>>>(Mat);
    gemm_kernel<<<dim3(DIM / 128, NROWS / 128), 256, GSMEM>>>(1, bout, y);
}

// round 8
// speedup vs baseline: 3.1768x; 1.2400x over previous
#include <cuda_runtime.h>
#include <cuda_fp16.h>
#include <cstdint>

// ============================================================================
// Attention_32916629357041 — fp16 2-term split GEMMs (mma.sync, sm_100 base)
//   prep:  x -> fp16 hi/lo; w_qkv (q-rows pre-scaled), w_out -> single fp16
//   gemm1: qkv = x @ w_qkv^T   (2 mma terms: Ah*B + Al*B, fp32 acc)
//   attn:  per-window softmax core (fp32, writes ao as fp16 hi/lo)
//   gemm2: y = ao @ w_out^T + b_out
// R8: fp16 2-term (was bf16 3-term) => 33% less tensor work; 3-stage pipeline.
// ============================================================================

typedef unsigned long long ull;

#define NB    1024
#define NTOK  64
#define DIM   512
#define QKDIM 1536
#define NROWS (NB * NTOK)          // 65536
#define SCALE 0.125f

// ---------------- device scratch ----------------
__device__ __half g_x_h[(size_t)NROWS * DIM];
__device__ __half g_x_l[(size_t)NROWS * DIM];
__device__ __half g_w1[QKDIM * DIM];
__device__ __half g_w2[DIM * DIM];
__device__ float  g_qkv[(size_t)NROWS * QKDIM];
__device__ __half g_ao_h[(size_t)NROWS * DIM];
__device__ __half g_ao_l[(size_t)NROWS * DIM];

// ---------------- helpers ----------------
__device__ __forceinline__ ull pk2(float x, float y) {
    ull r; asm("mov.b64 %0, {%1, %2};" : "=l"(r) : "f"(x), "f"(y)); return r;
}
__device__ __forceinline__ void fma2(ull& d, ull a, ull b) {
    asm("fma.rn.f32x2 %0, %1, %2, %0;" : "+l"(d) : "l"(a), "l"(b));
}
__device__ __forceinline__ float2 up2(ull v) {
    float2 f; asm("mov.b64 {%0, %1}, %2;" : "=f"(f.x), "=f"(f.y) : "l"(v)); return f;
}
__device__ __forceinline__ uint32_t smem_u32(const void* p) {
    uint32_t a;
    asm("{ .reg .u64 t; cvta.to.shared.u64 t, %1; cvt.u32.u64 %0, t; }" : "=r"(a) : "l"(p));
    return a;
}
__device__ __forceinline__ void cpa16(uint32_t dst, const void* src) {
    asm volatile("cp.async.cg.shared.global [%0], [%1], 16;" :: "r"(dst), "l"(src));
}
__device__ __forceinline__ void cpa_commit() {
    asm volatile("cp.async.commit_group;" ::: "memory");
}
template <int N>
__device__ __forceinline__ void cpa_wait() {
    asm volatile("cp.async.wait_group %0;" :: "n"(N) : "memory");
}
__device__ __forceinline__ void ldsm4(uint32_t* r, uint32_t addr) {
    asm volatile("ldmatrix.sync.aligned.m8n8.x4.shared.b16 {%0,%1,%2,%3}, [%4];"
                 : "=r"(r[0]), "=r"(r[1]), "=r"(r[2]), "=r"(r[3]) : "r"(addr));
}
__device__ __forceinline__ void mma16816(float* c, const uint32_t* a, const uint32_t* b) {
    asm volatile(
        "mma.sync.aligned.m16n8k16.row.col.f32.f16.f16.f32 "
        "{%0,%1,%2,%3}, {%4,%5,%6,%7}, {%8,%9}, {%0,%1,%2,%3};"
        : "+f"(c[0]), "+f"(c[1]), "+f"(c[2]), "+f"(c[3])
        : "r"(a[0]), "r"(a[1]), "r"(a[2]), "r"(a[3]), "r"(b[0]), "r"(b[1]));
}

// ============================================================================
// prep
// ============================================================================
__global__ void prep_kernel(const float* __restrict__ x,
                            const float* __restrict__ w1,
                            const float* __restrict__ w2) {
    size_t stride = (size_t)gridDim.x * blockDim.x;
    size_t tid = (size_t)blockIdx.x * blockDim.x + threadIdx.x;
    for (size_t i = tid; i < (size_t)NROWS * DIM; i += stride) {
        float v = x[i];
        __half h = __float2half(v);
        g_x_h[i] = h;
        g_x_l[i] = __float2half(v - __half2float(h));
    }
    for (size_t i = tid; i < (size_t)QKDIM * DIM; i += stride) {
        float v = w1[i] * ((i < (size_t)DIM * DIM) ? SCALE : 1.0f);  // fold q-scale
        g_w1[i] = __float2half(v);
    }
    for (size_t i = tid; i < (size_t)DIM * DIM; i += stride)
        g_w2[i] = __float2half(w2[i]);
}

// ============================================================================
// gemm: C[m][n] = sum_k A[m][k]*B[n][k], K=512, A fp16 hi/lo 2-term, fp32 acc
// CTA tile 128x128, 8 warps (4M x 2N). k-chunk 32, 3-stage cp.async pipeline,
// one __syncthreads per chunk. smem rows padded to 80B.
// ============================================================================
#define KC    32
#define ROWB  80                  // bytes per smem row (32 fp16 + 16 pad)
#define MATB  (128 * ROWB)        // 10240 per matrix
#define STG   (3 * MATB)          // Ah Al B per stage = 30720
#define GSMEM (3 * STG)           // 92160 (3 stages)

struct GemmSrc { const __half *Ah, *Al, *B; };

__device__ __forceinline__ void issue_stage(const GemmSrc& S, size_t arow0,
                                            size_t brow0, int kc, uint32_t sb,
                                            int t) {
    const __half* mats[3] = {S.Ah, S.Al, S.B};
    size_t row0s[3] = {arow0, arow0, brow0};
    #pragma unroll
    for (int m = 0; m < 3; ++m) {
        #pragma unroll
        for (int l = 0; l < 2; ++l) {
            int idx = t + l * 256;            // 0..511
            int r = idx >> 2, c16 = idx & 3;
            const __half* src =
                mats[m] + (row0s[m] + r) * DIM + kc * KC + c16 * 8;
            cpa16(sb + m * MATB + r * ROWB + c16 * 16, src);
        }
    }
    cpa_commit();
}

__global__ void __launch_bounds__(256, 2)
gemm_kernel(int which, const float* __restrict__ bias, float* __restrict__ cext) {
    extern __shared__ char sm[];
    const uint32_t sbase = smem_u32(sm);

    const int t = threadIdx.x, w = t >> 5, lane = t & 31;
    const int wm = w & 3, wn = w >> 2;
    const int nt = blockIdx.x, rt = blockIdx.y;

    GemmSrc S;
    float* C; int ldc;
    if (which == 0) { S = {g_x_h,  g_x_l,  g_w1};
                      C = g_qkv; ldc = QKDIM; }
    else            { S = {g_ao_h, g_ao_l, g_w2};
                      C = cext;  ldc = DIM; }
    const size_t arow0 = (size_t)rt * 128;
    const size_t brow0 = (size_t)nt * 128;

    float acc[2][8][4];
    #pragma unroll
    for (int mi = 0; mi < 2; ++mi)
        #pragma unroll
        for (int ni = 0; ni < 8; ++ni)
            #pragma unroll
            for (int e = 0; e < 4; ++e) acc[mi][ni][e] = 0.f;

    // ldmatrix lane addressing
    const int a_row  = wm * 32 + (lane & 15);
    const int a_koff = (lane >> 4) * 16;
    const int b_lr = lane & 7, b_g2 = lane >> 3;
    const int b_nrow_base = wn * 64 + b_lr + (b_g2 >> 1) * 8;
    const int b_koff = (b_g2 & 1) * 16;

    const int NKC = DIM / KC;   // 16
    issue_stage(S, arow0, brow0, 0, sbase, t);
    issue_stage(S, arow0, brow0, 1, sbase + STG, t);

    for (int kc = 0; kc < NKC; ++kc) {
        const uint32_t sb = sbase + (kc % 3) * STG;
        if (kc + 1 < NKC) cpa_wait<1>();   // stage kc landed; kc+1 may pend
        else              cpa_wait<0>();
        __syncthreads();                   // data visible; buf (kc+2)%3 free
        if (kc + 2 < NKC)
            issue_stage(S, arow0, brow0, kc + 2, sbase + ((kc + 2) % 3) * STG, t);

        #pragma unroll
        for (int k16 = 0; k16 < 2; ++k16) {
            const int kb = k16 * 32;      // byte offset of this k16 in the row
            uint32_t ah[2][4], al[2][4];
            #pragma unroll
            for (int mi = 0; mi < 2; ++mi) {
                uint32_t ad = sb + (a_row + mi * 16) * ROWB + kb + a_koff;
                ldsm4(ah[mi], ad);
                ldsm4(al[mi], ad + MATB);
            }
            // JIT B fragments: load per-g, consume immediately
            #pragma unroll
            for (int g = 0; g < 4; ++g) {
                uint32_t bb[4];
                uint32_t bd = sb + 2 * MATB + (b_nrow_base + g * 16) * ROWB + kb + b_koff;
                ldsm4(bb, bd);
                #pragma unroll
                for (int mi = 0; mi < 2; ++mi) {
                    mma16816(acc[mi][2 * g],     ah[mi], bb);
                    mma16816(acc[mi][2 * g + 1], ah[mi], bb + 2);
                    mma16816(acc[mi][2 * g],     al[mi], bb);
                    mma16816(acc[mi][2 * g + 1], al[mi], bb + 2);
                }
            }
        }
    }

    // ---- epilogue: direct register -> gmem stores ----
    const int qr = lane >> 2, qc = lane & 3;
    #pragma unroll
    for (int mi = 0; mi < 2; ++mi) {
        #pragma unroll
        for (int ni = 0; ni < 8; ++ni) {
            size_t row = arow0 + wm * 32 + mi * 16 + qr;
            int col = nt * 128 + wn * 64 + ni * 8 + qc * 2;
            float2 v0 = make_float2(acc[mi][ni][0], acc[mi][ni][1]);
            float2 v1 = make_float2(acc[mi][ni][2], acc[mi][ni][3]);
            if (bias != nullptr) {
                float2 bz = *(const float2*)(bias + col);
                v0.x += bz.x; v0.y += bz.y; v1.x += bz.x; v1.y += bz.y;
            }
            *(float2*)(C + row * ldc + col)       = v0;
            *(float2*)(C + (row + 8) * ldc + col) = v1;
        }
    }
}

// ============================================================================
// attention core: per window, fp32. Reads g_qkv, writes g_ao_{h,l} (fp16).
// ============================================================================
#define AQ 68
#define ASMEM ((4 * 64 * AQ + 240) * 4)

__global__ void __launch_bounds__(256, 2)
attn_kernel(const float* __restrict__ Mat) {
    extern __shared__ float smf[];
    float* qs   = smf;
    float* ks   = qs + 64 * AQ;
    float* vs   = ks + 64 * AQ;
    float* as_  = vs + 64 * AQ;
    float* mats = as_ + 64 * AQ;

    const int b = blockIdx.x, t = threadIdx.x;
    if (t < 225) mats[t] = Mat[t];

    const int tx = t & 15, ty = t >> 4;
    const int ai0 = ty * 4, tj = tx, d0 = tx * 4;
    const float* qg = g_qkv + (size_t)b * NTOK * QKDIM;

    for (int h = 0; h < 8; ++h) {
        #pragma unroll
        for (int l = 0; l < 4; ++l) {
            int idx = t + l * 256;           // 0..1023
            int row = idx >> 4, c4 = idx & 15;
            const float* rp = qg + (size_t)row * QKDIM + h * 64 + c4 * 4;
            *(float4*)(qs + row * AQ + c4 * 4) = *(const float4*)(rp);
            *(float4*)(ks + row * AQ + c4 * 4) = *(const float4*)(rp + 512);
            *(float4*)(vs + row * AQ + c4 * 4) = *(const float4*)(rp + 1024);
        }
        __syncthreads();

        // ---- sim = q k^T + bias; softmax ----
        {
            ull s2[4][4];
            #pragma unroll
            for (int r = 0; r < 4; ++r)
                #pragma unroll
                for (int c = 0; c < 4; ++c) s2[r][c] = 0ULL;

            #pragma unroll 4
            for (int dq = 0; dq < 16; ++dq) {
                float4 qv[4], kv[4];
                #pragma unroll
                for (int r = 0; r < 4; ++r)
                    qv[r] = *(const float4*)(qs + (ai0 + r) * AQ + 4 * dq);
                #pragma unroll
                for (int c = 0; c < 4; ++c)
                    kv[c] = *(const float4*)(ks + (tj + 16 * c) * AQ + 4 * dq);
                #pragma unroll
                for (int r = 0; r < 4; ++r) {
                    ull q01 = pk2(qv[r].x, qv[r].y), q23 = pk2(qv[r].z, qv[r].w);
                    #pragma unroll
                    for (int c = 0; c < 4; ++c) {
                        fma2(s2[r][c], q01, pk2(kv[c].x, kv[c].y));
                        fma2(s2[r][c], q23, pk2(kv[c].z, kv[c].w));
                    }
                }
            }
            #pragma unroll
            for (int r = 0; r < 4; ++r) {
                int i = ai0 + r;
                int r1 = i >> 3, c1 = i & 7;
                float sim[4];
                #pragma unroll
                for (int c = 0; c < 4; ++c) {
                    int j = tj + 16 * c;
                    int r2 = j >> 3, c2 = j & 7;
                    float2 p = up2(s2[r][c]);
                    sim[c] = p.x + p.y + mats[(r2 - r1 + 7) * 15 + (c2 - c1 + 7)];
                }
                float m = fmaxf(fmaxf(sim[0], sim[1]), fmaxf(sim[2], sim[3]));
                m = fmaxf(m, __shfl_xor_sync(0xffffffffu, m, 1));
                m = fmaxf(m, __shfl_xor_sync(0xffffffffu, m, 2));
                m = fmaxf(m, __shfl_xor_sync(0xffffffffu, m, 4));
                m = fmaxf(m, __shfl_xor_sync(0xffffffffu, m, 8));
                float e0 = __expf(sim[0] - m), e1 = __expf(sim[1] - m);
                float e2 = __expf(sim[2] - m), e3 = __expf(sim[3] - m);
                float s = e0 + e1 + e2 + e3;
                s += __shfl_xor_sync(0xffffffffu, s, 1);
                s += __shfl_xor_sync(0xffffffffu, s, 2);
                s += __shfl_xor_sync(0xffffffffu, s, 4);
                s += __shfl_xor_sync(0xffffffffu, s, 8);
                float inv = 1.f / s;
                as_[(ai0 + r) * AQ + tj]      = e0 * inv;
                as_[(ai0 + r) * AQ + tj + 16] = e1 * inv;
                as_[(ai0 + r) * AQ + tj + 32] = e2 * inv;
                as_[(ai0 + r) * AQ + tj + 48] = e3 * inv;
            }
        }
        __syncthreads();

        // ---- out = attn @ v ; split to fp16 hi/lo ----
        {
            ull o2[4][2];
            #pragma unroll
            for (int r = 0; r < 4; ++r) { o2[r][0] = 0ULL; o2[r][1] = 0ULL; }
            #pragma unroll 4
            for (int j = 0; j < 64; ++j) {
                float4 vv = *(const float4*)(vs + j * AQ + d0);
                ull vp0 = pk2(vv.x, vv.y), vp1 = pk2(vv.z, vv.w);
                #pragma unroll
                for (int r = 0; r < 4; ++r) {
                    float a = as_[(ai0 + r) * AQ + j];
                    ull pa = pk2(a, a);
                    fma2(o2[r][0], pa, vp0);
                    fma2(o2[r][1], pa, vp1);
                }
            }
            #pragma unroll
            for (int r = 0; r < 4; ++r) {
                float2 lo2 = up2(o2[r][0]), hi2 = up2(o2[r][1]);
                float o[4] = {lo2.x, lo2.y, hi2.x, hi2.y};
                size_t off = ((size_t)b * NTOK + ai0 + r) * DIM + h * 64 + d0;
                __half hh[4], hl[4];
                #pragma unroll
                for (int c = 0; c < 4; ++c) {
                    hh[c] = __float2half(o[c]);
                    hl[c] = __float2half(o[c] - __half2float(hh[c]));
                }
                *(__half2*)(g_ao_h + off)     = __halves2half2(hh[0], hh[1]);
                *(__half2*)(g_ao_h + off + 2) = __halves2half2(hh[2], hh[3]);
                *(__half2*)(g_ao_l + off)     = __halves2half2(hl[0], hl[1]);
                *(__half2*)(g_ao_l + off + 2) = __halves2half2(hl[2], hl[3]);
            }
        }
        __syncthreads();
    }
}

// ============================================================================
extern "C" void kernel_launch(void* const* d_in, const int* in_sizes, int n_in,
                              void* d_out, int out_size) {
    const float* x    = (const float*)d_in[0];
    const float* wqkv = (const float*)d_in[1];
    const float* wout = (const float*)d_in[2];
    const float* bout = (const float*)d_in[3];
    const float* Mat  = (const float*)d_in[4];
    float* y = (float*)d_out;

    static bool attr_set = false;
    if (!attr_set) {
        cudaFuncSetAttribute(gemm_kernel,
                             cudaFuncAttributeMaxDynamicSharedMemorySize, GSMEM);
        cudaFuncSetAttribute(attn_kernel,
                             cudaFuncAttributeMaxDynamicSharedMemorySize, ASMEM);
        attr_set = true;
    }

    prep_kernel<<<8192, 256>>>(x, wqkv, wout);
    gemm_kernel<<<dim3(QKDIM / 128, NROWS / 128), 256, GSMEM>>>(0, nullptr, y);
    attn_kernel<<<NB, 256, ASMEM>>>(Mat);
    gemm_kernel<<<dim3(DIM / 128, NROWS / 128), 256, GSMEM>>>(1, bout, y);
}